// round 6
// baseline (speedup 1.0000x reference)
#include <cuda_runtime.h>

#define BATCH 32
#define CCH   84
#define ANCH  8400
#define A4    (ANCH / 4)      // 2100 float4 per channel
#define KTOP  1000
#define CAP   2048            // max compacted candidates per image (expected ~105)
#define GRID  128             // <= 148 SMs; 1 block/SM (1024 thr, 48KB smem) -> wave-1 co-resident
#define NTH   1024

// Key = (f32 bits of conf << 32) | (~anchor_idx): DESCENDING key order gives
// conf desc then anchor idx asc (lax.top_k tie rule). Keys are unique.
__device__ int                g_count[BATCH];      // zero-init; reset by consumer each run
__device__ unsigned long long g_keys[BATCH][CAP];
__device__ unsigned           g_bar_count;         // zero-init; reset by flipper each run
__device__ unsigned           g_bar_sense;         // flips once per run; spinners compare pre-read

__global__ void __launch_bounds__(NTH, 1) fused_detect_kernel(
    const float* __restrict__ preds, float* __restrict__ out)
{
    const int tid  = threadIdx.x;
    const int gtid = blockIdx.x * NTH + tid;

    // ---------------- Phase 1: zero output + score compact ----------------
    {
        float4 z = make_float4(0.f, 0.f, 0.f, 0.f);
        const int total4 = BATCH * KTOP * 6 / 4;          // 48000
        for (int i = gtid; i < total4; i += GRID * NTH)
            ((float4*)out)[i] = z;
    }

    if (gtid < BATCH * A4) {
        const int b = gtid / A4;
        const int q = gtid - b * A4;
        const float4* p = (const float4*)(preds + (size_t)b * CCH * ANCH);

        float4 s0 = p[4 * A4 + q];                        // class-0 scores, 4 anchors
        float4 rest = make_float4(-1.f, -1.f, -1.f, -1.f);

        // Chunks of 8 classes; break once ALL 4 anchors are strictly invalid
        // (some class > s0). rest only grows, so decisions are monotone.
#pragma unroll
        for (int chunk = 0; chunk < 10; ++chunk) {
            const int c0 = 5 + chunk * 8;
            const int c1 = (c0 + 8 < CCH) ? (c0 + 8) : CCH;
#pragma unroll
            for (int c = c0; c < c1; ++c) {
                float4 v = p[c * A4 + q];
                rest.x = fmaxf(rest.x, v.x);
                rest.y = fmaxf(rest.y, v.y);
                rest.z = fmaxf(rest.z, v.z);
                rest.w = fmaxf(rest.w, v.w);
            }
            if (rest.x > s0.x && rest.y > s0.y && rest.z > s0.z && rest.w > s0.w)
                break;
        }

        const int a = q * 4;
        float s[4] = { s0.x, s0.y, s0.z, s0.w };
        float r[4] = { rest.x, rest.y, rest.z, rest.w };
#pragma unroll
        for (int k = 0; k < 4; ++k) {
            if (s[k] > 0.1f && s[k] >= r[k]) {    // argmax==0 (first-occurrence) & conf>thr
                int pos = atomicAdd(&g_count[b], 1);
                if (pos < CAP)
                    g_keys[b][pos] =
                        ((unsigned long long)__float_as_uint(s[k]) << 32)
                        | (unsigned)(0xFFFFFFFFu - (unsigned)(a + k));
            }
        }
    }

    // ---------------- Grid barrier (sense-reversal) ----------------
    __syncthreads();                                   // CTA-local HB to thread 0
    if (tid == 0) {
        __threadfence();                               // release block's writes
        unsigned old = *((volatile unsigned*)&g_bar_sense);   // read BEFORE arriving
        unsigned t = atomicAdd(&g_bar_count, 1);
        if (t == GRID - 1) {
            g_bar_count = 0;                           // reset for next replay
            __threadfence();
            atomicExch(&g_bar_sense, old ^ 1u);
        } else if (blockIdx.x < BATCH) {               // non-NMS blocks just exit
            while (*((volatile unsigned*)&g_bar_sense) == old) { __nanosleep(64); }
        }
        __threadfence();                               // acquire
    }
    __syncthreads();
    if (blockIdx.x >= BATCH) return;

    // ---------------- Phase 2: per-image sort + NMS + emit ----------------
    const int b  = blockIdx.x;
    const int NT = NTH;

    __shared__ unsigned long long keys[CAP];
    __shared__ float bx1[1024], by1[1024], bx2[1024], by2[1024], barea[1024];
    __shared__ short perm[1024];           // sorted pos -> smem slot
    __shared__ unsigned char keep[1024];
    __shared__ unsigned mask[256][8];      // suppression bits (sorted space), n<=256
    __shared__ unsigned keepw[8];

    float* o = out + (size_t)b * KTOP * 6;

    int cnt = __ldcg(&g_count[b]);                     // L1-bypass: written by other SMs
    if (cnt > CAP) cnt = CAP;
    for (int i = tid; i < cnt; i += NT) keys[i] = __ldcg(&g_keys[b][i]);
    __syncthreads();
    if (tid == 0) g_count[b] = 0;                      // reset for next replay

    const float* p = preds + (size_t)b * CCH * ANCH;
    const int n = (cnt < KTOP) ? cnt : KTOP;

    if (cnt <= 256) {
        // Gather boxes in UNSORTED order (overlaps rank loop with scattered LDGs).
        if (tid < cnt) {
            int r = tid;
            int idx = (int)(0xFFFFFFFFu - (unsigned)keys[r]);
            float cx = p[idx];
            float cy = p[ANCH + idx];
            float w  = p[2 * ANCH + idx];
            float h  = p[3 * ANCH + idx];

            unsigned long long k = keys[r];
            int rank = 0;
            for (int j = 0; j < cnt; ++j) rank += (keys[j] > k);
            perm[rank] = (short)r;

            float hw = __fmul_rn(w, 0.5f), hh = __fmul_rn(h, 0.5f);
            float x1 = __fsub_rn(cx, hw), y1 = __fsub_rn(cy, hh);
            float x2 = __fadd_rn(cx, hw), y2 = __fadd_rn(cy, hh);
            bx1[r] = x1; by1[r] = y1; bx2[r] = x2; by2[r] = y2;
            barea[r] = __fmul_rn(__fsub_rn(x2, x1), __fsub_rn(y2, y1));
        }
        for (int i = tid; i < n * 8; i += NT) ((unsigned*)mask)[i] = 0u;  // ALL n rows
        __syncthreads();

        // Pairwise IoU in sorted space: bit j of mask[i] = iou(sorted i, sorted j) > thr.
        {
            int total = n * n;
            int t = tid;
            if (t < total) {
                int i = t / n;             // one division per thread
                int j = t - i * n;
                for (; t < total; t += NT) {
                    if (j > i) {
                        int pi = perm[i], pj = perm[j];
                        float xx1 = fmaxf(bx1[pi], bx1[pj]);
                        float yy1 = fmaxf(by1[pi], by1[pj]);
                        float xx2 = fminf(bx2[pi], bx2[pj]);
                        float yy2 = fminf(by2[pi], by2[pj]);
                        float iw  = fmaxf(__fsub_rn(xx2, xx1), 0.0f);
                        float ih  = fmaxf(__fsub_rn(yy2, yy1), 0.0f);
                        float inter = __fmul_rn(iw, ih);
                        float denom = __fadd_rn(
                            __fsub_rn(__fadd_rn(barea[pi], barea[pj]), inter), 1e-7f);
                        if (__fdiv_rn(inter, denom) > 0.7f)
                            atomicOr(&mask[i][j >> 5], 1u << (j & 31));
                    }
                    j += NT;
                    while (j >= n) { j -= n; ++i; }   // carry (NT/n small)
                }
            }
        }
        __syncthreads();

        // Warp-cooperative greedy sweep: lane w<8 owns keep word w in a register.
        if (tid < 32) {
            const int lane = tid;
            unsigned kw = 0;
            if (lane < 8) {
                int lo = lane * 32;
                kw = (n >= lo + 32) ? 0xFFFFFFFFu
                   : (n <= lo ? 0u : ((1u << (n - lo)) - 1u));
            }
            unsigned mnext = (lane < 8 && n > 0) ? mask[0][lane] : 0u;
            for (int i = 0; i < n; ++i) {
                unsigned m = mnext;
                int nx = (i + 1 < n) ? (i + 1) : i;
                mnext = (lane < 8) ? mask[nx][lane] : 0u;   // prefetch
                unsigned kwi = __shfl_sync(0xFFFFFFFFu, kw, i >> 5);
                if ((kwi >> (i & 31)) & 1u)
                    kw &= ~m;
            }
            if (lane < 8) keepw[lane] = kw;
        }
        __syncthreads();

        // Emit kept rows (slab already zeroed in phase 1).
        const float SCALE_F = 0.3333333333333333f;
        if (tid < n) {
            int r = tid;
            if ((keepw[r >> 5] >> (r & 31)) & 1u) {
                int pr = perm[r];
                float conf = __uint_as_float((unsigned)(keys[pr] >> 32));
                o[r * 6 + 0] = __fdiv_rn(bx1[pr], SCALE_F);
                o[r * 6 + 1] = __fdiv_rn(by1[pr], SCALE_F);
                o[r * 6 + 2] = __fdiv_rn(bx2[pr], SCALE_F);
                o[r * 6 + 3] = __fdiv_rn(by2[pr], SCALE_F);
                o[r * 6 + 4] = conf;
                // o[r*6+5] stays 0 (cls)
            }
        }
    } else {
        // ---- Fallback (statistically never taken): bitonic sort + sequential NMS ----
        int m = 1; while (m < cnt) m <<= 1;
        for (int i = cnt + tid; i < m; i += NT) keys[i] = 0ull;
        __syncthreads();
        for (int k = 2; k <= m; k <<= 1)
            for (int j = k >> 1; j > 0; j >>= 1) {
                for (int i = tid; i < m; i += NT) {
                    int ixj = i ^ j;
                    if (ixj > i) {
                        unsigned long long u = keys[i], v = keys[ixj];
                        bool desc = ((i & k) == 0);
                        if ((u < v) == desc) { keys[i] = v; keys[ixj] = u; }
                    }
                }
                __syncthreads();
            }
        for (int r = tid; r < n; r += NT) {
            int idx = (int)(0xFFFFFFFFu - (unsigned)keys[r]);
            float cx = p[idx];
            float cy = p[ANCH + idx];
            float w  = p[2 * ANCH + idx];
            float h  = p[3 * ANCH + idx];
            float hw = __fmul_rn(w, 0.5f), hh = __fmul_rn(h, 0.5f);
            float x1 = __fsub_rn(cx, hw), y1 = __fsub_rn(cy, hh);
            float x2 = __fadd_rn(cx, hw), y2 = __fadd_rn(cy, hh);
            bx1[r] = x1; by1[r] = y1; bx2[r] = x2; by2[r] = y2;
            barea[r] = __fmul_rn(__fsub_rn(x2, x1), __fsub_rn(y2, y1));
            keep[r] = 1;
        }
        __syncthreads();
        for (int i = 0; i + 1 < n; ++i) {
            if (keep[i]) {
                float xi1 = bx1[i], yi1 = by1[i], xi2 = bx2[i], yi2 = by2[i];
                float ai  = barea[i];
                for (int j = i + 1 + tid; j < n; j += NT) {
                    if (!keep[j]) continue;
                    float xx1 = fmaxf(xi1, bx1[j]);
                    float yy1 = fmaxf(yi1, by1[j]);
                    float xx2 = fminf(xi2, bx2[j]);
                    float yy2 = fminf(yi2, by2[j]);
                    float iw  = fmaxf(__fsub_rn(xx2, xx1), 0.0f);
                    float ih  = fmaxf(__fsub_rn(yy2, yy1), 0.0f);
                    float inter = __fmul_rn(iw, ih);
                    float denom = __fadd_rn(__fsub_rn(__fadd_rn(ai, barea[j]), inter), 1e-7f);
                    if (__fdiv_rn(inter, denom) > 0.7f) keep[j] = 0;
                }
            }
            __syncthreads();
        }
        const float SCALE_F = 0.3333333333333333f;
        for (int r = tid; r < n; r += NT) {
            if (keep[r]) {
                float conf = __uint_as_float((unsigned)(keys[r] >> 32));
                o[r * 6 + 0] = __fdiv_rn(bx1[r], SCALE_F);
                o[r * 6 + 1] = __fdiv_rn(by1[r], SCALE_F);
                o[r * 6 + 2] = __fdiv_rn(bx2[r], SCALE_F);
                o[r * 6 + 3] = __fdiv_rn(by2[r], SCALE_F);
                o[r * 6 + 4] = conf;
            }
        }
    }
}

extern "C" void kernel_launch(void* const* d_in, const int* in_sizes, int n_in,
                              void* d_out, int out_size) {
    const float* preds = (const float*)d_in[0];
    float* out = (float*)d_out;
    fused_detect_kernel<<<GRID, NTH>>>(preds, out);
}

// round 7
// speedup vs baseline: 1.1495x; 1.1495x over previous
#include <cuda_runtime.h>

#define BATCH 32
#define CCH   84
#define ANCH  8400
#define KTOP  1000
#define CAP   2048            // max compacted candidates per image (expected ~105)

// Key = (f32 bits of conf << 32) | (~anchor_idx): DESCENDING key order gives
// conf desc then anchor idx asc (lax.top_k tie rule). Keys are unique.
// g_count is zero-init at module load; nms kernel resets it after consuming.
__device__ int                g_count[BATCH];
__device__ unsigned long long g_keys[BATCH][CAP];

// One thread per (image, anchor). Two-stage scan: 16 classes pipelined, then
// the remaining 63 only for the ~6% of anchors still possibly class-0-max.
// Also zeroes the output slab (spread across the whole grid).
__global__ void __launch_bounds__(256) score_compact_kernel(
    const float* __restrict__ preds, float* __restrict__ out)
{
    const int gtid = blockIdx.x * 256 + threadIdx.x;

    // Zero output slab (48000 float4 across 268800 threads).
    if (gtid < (BATCH * KTOP * 6) / 4)
        ((float4*)out)[gtid] = make_float4(0.f, 0.f, 0.f, 0.f);

    if (gtid >= BATCH * ANCH) return;
    const int b = gtid / ANCH;
    const int a = gtid - b * ANCH;

    const float* p = preds + (size_t)b * CCH * ANCH + a;
    const float s0 = p[4 * ANCH];          // class-0 score

    // Stage 1: classes 5..20 (16 independent, fully pipelined LDGs).
    float rest = -1.0f;
#pragma unroll
    for (int c = 5; c < 21; ++c)
        rest = fmaxf(rest, p[(size_t)c * ANCH]);

    if (s0 > 0.1f && s0 >= rest) {
        // Stage 2: classes 21..83 (only ~6% of anchors get here).
#pragma unroll 21
        for (int c = 21; c < CCH; ++c)
            rest = fmaxf(rest, p[(size_t)c * ANCH]);

        if (s0 >= rest) {                  // argmax==0 (first-occurrence) & conf>thr
            int pos = atomicAdd(&g_count[b], 1);
            if (pos < CAP)
                g_keys[b][pos] =
                    ((unsigned long long)__float_as_uint(s0) << 32)
                    | (unsigned)(0xFFFFFFFFu - (unsigned)a);
        }
    }
}

// One block per image: rank-sort (overlapped with gather), IoU masks, warp sweep, emit.
__global__ void __launch_bounds__(1024, 1) sort_nms_out_kernel(
    const float* __restrict__ preds, float* __restrict__ out)
{
    const int b   = blockIdx.x;
    const int tid = threadIdx.x;
    const int NT  = 1024;

    __shared__ unsigned long long keys[CAP];
    __shared__ float bx1[1024], by1[1024], bx2[1024], by2[1024], barea[1024];
    __shared__ short perm[1024];           // sorted pos -> smem slot
    __shared__ unsigned char keep[1024];
    __shared__ unsigned mask[256][8];      // suppression bits (sorted space), n<=256
    __shared__ unsigned keepw[8];

    float* o = out + (size_t)b * KTOP * 6;

    int cnt = g_count[b];
    if (cnt > CAP) cnt = CAP;
    for (int i = tid; i < cnt; i += NT) keys[i] = g_keys[b][i];
    __syncthreads();
    if (tid == 0) g_count[b] = 0;          // reset for next replay

    const float* p = preds + (size_t)b * CCH * ANCH;
    const int n = (cnt < KTOP) ? cnt : KTOP;

    if (cnt <= 256) {
        // Gather boxes in UNSORTED candidate order (overlaps the rank loop's
        // latency with the scattered LDGs) and compute ranks in parallel.
        if (tid < cnt) {
            int r = tid;
            int idx = (int)(0xFFFFFFFFu - (unsigned)keys[r]);
            float cx = p[idx];              // LDGs issued up front
            float cy = p[ANCH + idx];
            float w  = p[2 * ANCH + idx];
            float h  = p[3 * ANCH + idx];

            unsigned long long k = keys[r];
            int rank = 0;
            for (int j = 0; j < cnt; ++j) rank += (keys[j] > k);
            perm[rank] = (short)r;

            float hw = __fmul_rn(w, 0.5f), hh = __fmul_rn(h, 0.5f);
            float x1 = __fsub_rn(cx, hw), y1 = __fsub_rn(cy, hh);
            float x2 = __fadd_rn(cx, hw), y2 = __fadd_rn(cy, hh);
            bx1[r] = x1; by1[r] = y1; bx2[r] = x2; by2[r] = y2;
            barea[r] = __fmul_rn(__fsub_rn(x2, x1), __fsub_rn(y2, y1));
        }
        // Zero ALL n rows of the mask (n*8 words).
        for (int i = tid; i < n * 8; i += NT) ((unsigned*)mask)[i] = 0u;
        __syncthreads();

        // Pairwise IoU in sorted space: bit j of mask[i] = iou(sorted i, sorted j) > thr.
        {
            int total = n * n;
            int t = tid;
            if (t < total) {
                int i = t / n;             // one division per thread
                int j = t - i * n;
                for (; t < total; t += NT) {
                    if (j > i) {
                        int pi = perm[i], pj = perm[j];
                        float xx1 = fmaxf(bx1[pi], bx1[pj]);
                        float yy1 = fmaxf(by1[pi], by1[pj]);
                        float xx2 = fminf(bx2[pi], bx2[pj]);
                        float yy2 = fminf(by2[pi], by2[pj]);
                        float iw  = fmaxf(__fsub_rn(xx2, xx1), 0.0f);
                        float ih  = fmaxf(__fsub_rn(yy2, yy1), 0.0f);
                        float inter = __fmul_rn(iw, ih);
                        float denom = __fadd_rn(
                            __fsub_rn(__fadd_rn(barea[pi], barea[pj]), inter), 1e-7f);
                        if (__fdiv_rn(inter, denom) > 0.7f)
                            atomicOr(&mask[i][j >> 5], 1u << (j & 31));
                    }
                    j += NT;
                    while (j >= n) { j -= n; ++i; }   // carry (NT/n small)
                }
            }
        }
        __syncthreads();

        // Warp-cooperative greedy sweep: lane w<8 owns keep word w in a register.
        if (tid < 32) {
            const int lane = tid;
            unsigned kw = 0;
            if (lane < 8) {
                int lo = lane * 32;
                kw = (n >= lo + 32) ? 0xFFFFFFFFu
                   : (n <= lo ? 0u : ((1u << (n - lo)) - 1u));
            }
            unsigned mnext = (lane < 8 && n > 0) ? mask[0][lane] : 0u;
            for (int i = 0; i < n; ++i) {
                unsigned m = mnext;
                int nx = (i + 1 < n) ? (i + 1) : i;
                mnext = (lane < 8) ? mask[nx][lane] : 0u;   // prefetch
                unsigned kwi = __shfl_sync(0xFFFFFFFFu, kw, i >> 5);
                if ((kwi >> (i & 31)) & 1u)
                    kw &= ~m;
            }
            if (lane < 8) keepw[lane] = kw;
        }
        __syncthreads();

        // Emit kept rows (slab already zeroed by compact kernel).
        const float SCALE_F = 0.3333333333333333f;
        if (tid < n) {
            int r = tid;
            if ((keepw[r >> 5] >> (r & 31)) & 1u) {
                int pr = perm[r];
                float conf = __uint_as_float((unsigned)(keys[pr] >> 32));
                o[r * 6 + 0] = __fdiv_rn(bx1[pr], SCALE_F);
                o[r * 6 + 1] = __fdiv_rn(by1[pr], SCALE_F);
                o[r * 6 + 2] = __fdiv_rn(bx2[pr], SCALE_F);
                o[r * 6 + 3] = __fdiv_rn(by2[pr], SCALE_F);
                o[r * 6 + 4] = conf;
                // o[r*6+5] stays 0 (cls)
            }
        }
    } else {
        // ---- Fallback (statistically never taken): bitonic sort + sequential NMS ----
        int m = 1; while (m < cnt) m <<= 1;
        for (int i = cnt + tid; i < m; i += NT) keys[i] = 0ull;
        __syncthreads();
        for (int k = 2; k <= m; k <<= 1)
            for (int j = k >> 1; j > 0; j >>= 1) {
                for (int i = tid; i < m; i += NT) {
                    int ixj = i ^ j;
                    if (ixj > i) {
                        unsigned long long u = keys[i], v = keys[ixj];
                        bool desc = ((i & k) == 0);
                        if ((u < v) == desc) { keys[i] = v; keys[ixj] = u; }
                    }
                }
                __syncthreads();
            }
        for (int r = tid; r < n; r += NT) {
            int idx = (int)(0xFFFFFFFFu - (unsigned)keys[r]);
            float cx = p[idx];
            float cy = p[ANCH + idx];
            float w  = p[2 * ANCH + idx];
            float h  = p[3 * ANCH + idx];
            float hw = __fmul_rn(w, 0.5f), hh = __fmul_rn(h, 0.5f);
            float x1 = __fsub_rn(cx, hw), y1 = __fsub_rn(cy, hh);
            float x2 = __fadd_rn(cx, hw), y2 = __fadd_rn(cy, hh);
            bx1[r] = x1; by1[r] = y1; bx2[r] = x2; by2[r] = y2;
            barea[r] = __fmul_rn(__fsub_rn(x2, x1), __fsub_rn(y2, y1));
            keep[r] = 1;
        }
        __syncthreads();
        for (int i = 0; i + 1 < n; ++i) {
            if (keep[i]) {
                float xi1 = bx1[i], yi1 = by1[i], xi2 = bx2[i], yi2 = by2[i];
                float ai  = barea[i];
                for (int j = i + 1 + tid; j < n; j += NT) {
                    if (!keep[j]) continue;
                    float xx1 = fmaxf(xi1, bx1[j]);
                    float yy1 = fmaxf(yi1, by1[j]);
                    float xx2 = fminf(xi2, bx2[j]);
                    float yy2 = fminf(yi2, by2[j]);
                    float iw  = fmaxf(__fsub_rn(xx2, xx1), 0.0f);
                    float ih  = fmaxf(__fsub_rn(yy2, yy1), 0.0f);
                    float inter = __fmul_rn(iw, ih);
                    float denom = __fadd_rn(__fsub_rn(__fadd_rn(ai, barea[j]), inter), 1e-7f);
                    if (__fdiv_rn(inter, denom) > 0.7f) keep[j] = 0;
                }
            }
            __syncthreads();
        }
        const float SCALE_F = 0.3333333333333333f;
        for (int r = tid; r < n; r += NT) {
            if (keep[r]) {
                float conf = __uint_as_float((unsigned)(keys[r] >> 32));
                o[r * 6 + 0] = __fdiv_rn(bx1[r], SCALE_F);
                o[r * 6 + 1] = __fdiv_rn(by1[r], SCALE_F);
                o[r * 6 + 2] = __fdiv_rn(bx2[r], SCALE_F);
                o[r * 6 + 3] = __fdiv_rn(by2[r], SCALE_F);
                o[r * 6 + 4] = conf;
            }
        }
    }
}

extern "C" void kernel_launch(void* const* d_in, const int* in_sizes, int n_in,
                              void* d_out, int out_size) {
    const float* preds = (const float*)d_in[0];
    float* out = (float*)d_out;

    score_compact_kernel<<<(BATCH * ANCH + 255) / 256, 256>>>(preds, out);
    sort_nms_out_kernel<<<BATCH, 1024>>>(preds, out);
}

// round 8
// speedup vs baseline: 1.3686x; 1.1905x over previous
#include <cuda_runtime.h>

#define BATCH 32
#define CCH   84
#define ANCH  8400
#define KTOP  1000
#define CAP   2048            // max compacted candidates per image (expected ~105)

// Key = (f32 bits of conf << 32) | (~anchor_idx): DESCENDING key order gives
// conf desc then anchor idx asc (lax.top_k tie rule). Keys are unique.
// g_count is zero-init at module load; nms kernel resets it after consuming.
__device__ int                g_count[BATCH];
__device__ unsigned long long g_keys[BATCH][CAP];

// One thread per (image, anchor). Two-stage scan: 16 classes pipelined, then
// the remaining 63 only for the ~6% of anchors still possibly class-0-max.
// Also zeroes the output slab (spread across the whole grid).
__global__ void __launch_bounds__(256) score_compact_kernel(
    const float* __restrict__ preds, float* __restrict__ out)
{
    const int gtid = blockIdx.x * 256 + threadIdx.x;

    // Zero output slab (48000 float4 across 268800 threads).
    if (gtid < (BATCH * KTOP * 6) / 4)
        ((float4*)out)[gtid] = make_float4(0.f, 0.f, 0.f, 0.f);

    if (gtid >= BATCH * ANCH) return;
    const int b = gtid / ANCH;
    const int a = gtid - b * ANCH;

    const float* p = preds + (size_t)b * CCH * ANCH + a;
    const float s0 = p[4 * ANCH];          // class-0 score

    // Stage 1: classes 5..20 (16 independent, fully pipelined LDGs).
    float rest = -1.0f;
#pragma unroll
    for (int c = 5; c < 21; ++c)
        rest = fmaxf(rest, p[(size_t)c * ANCH]);

    if (s0 > 0.1f && s0 >= rest) {
        // Stage 2: classes 21..83 (only ~6% of anchors get here).
#pragma unroll 21
        for (int c = 21; c < CCH; ++c)
            rest = fmaxf(rest, p[(size_t)c * ANCH]);

        if (s0 >= rest) {                  // argmax==0 (first-occurrence) & conf>thr
            int pos = atomicAdd(&g_count[b], 1);
            if (pos < CAP)
                g_keys[b][pos] =
                    ((unsigned long long)__float_as_uint(s0) << 32)
                    | (unsigned)(0xFFFFFFFFu - (unsigned)a);
        }
    }
}

// One block per image: rank-sort (overlapped with gather), IoU masks, sparse
// warp sweep over suppressing rows only, emit.
__global__ void __launch_bounds__(1024, 1) sort_nms_out_kernel(
    const float* __restrict__ preds, float* __restrict__ out)
{
    const int b   = blockIdx.x;
    const int tid = threadIdx.x;
    const int NT  = 1024;

    __shared__ unsigned long long keys[CAP];
    __shared__ float bx1[1024], by1[1024], bx2[1024], by2[1024], barea[1024];
    __shared__ short perm[1024];           // sorted pos -> smem slot
    __shared__ unsigned char keep[1024];
    __shared__ unsigned mask[256][8];      // suppression bits (sorted space), n<=256
    __shared__ unsigned rowAny[8];         // bit i: row i has ANY suppression bit
    __shared__ unsigned keepw[8];

    float* o = out + (size_t)b * KTOP * 6;

    int cnt = g_count[b];
    if (cnt > CAP) cnt = CAP;
    for (int i = tid; i < cnt; i += NT) keys[i] = g_keys[b][i];
    __syncthreads();
    if (tid == 0) g_count[b] = 0;          // reset for next replay

    const float* p = preds + (size_t)b * CCH * ANCH;
    const int n = (cnt < KTOP) ? cnt : KTOP;

    if (cnt <= 256) {
        // Gather boxes in UNSORTED candidate order (overlaps the rank loop's
        // latency with the scattered LDGs) and compute ranks in parallel.
        if (tid < cnt) {
            int r = tid;
            int idx = (int)(0xFFFFFFFFu - (unsigned)keys[r]);
            float cx = p[idx];              // LDGs issued up front
            float cy = p[ANCH + idx];
            float w  = p[2 * ANCH + idx];
            float h  = p[3 * ANCH + idx];

            unsigned long long k = keys[r];
            int rank = 0;
            for (int j = 0; j < cnt; ++j) rank += (keys[j] > k);
            perm[rank] = (short)r;

            float hw = __fmul_rn(w, 0.5f), hh = __fmul_rn(h, 0.5f);
            float x1 = __fsub_rn(cx, hw), y1 = __fsub_rn(cy, hh);
            float x2 = __fadd_rn(cx, hw), y2 = __fadd_rn(cy, hh);
            bx1[r] = x1; by1[r] = y1; bx2[r] = x2; by2[r] = y2;
            barea[r] = __fmul_rn(__fsub_rn(x2, x1), __fsub_rn(y2, y1));
        }
        // Zero ALL n rows of the mask (n*8 words) + rowAny.
        for (int i = tid; i < n * 8; i += NT) ((unsigned*)mask)[i] = 0u;
        if (tid < 8) rowAny[tid] = 0u;
        __syncthreads();

        // Pairwise IoU in sorted space: bit j of mask[i] = iou(sorted i, sorted j) > thr.
        {
            int total = n * n;
            int t = tid;
            if (t < total) {
                int i = t / n;             // one division per thread
                int j = t - i * n;
                for (; t < total; t += NT) {
                    if (j > i) {
                        int pi = perm[i], pj = perm[j];
                        float xx1 = fmaxf(bx1[pi], bx1[pj]);
                        float yy1 = fmaxf(by1[pi], by1[pj]);
                        float xx2 = fminf(bx2[pi], bx2[pj]);
                        float yy2 = fminf(by2[pi], by2[pj]);
                        float iw  = fmaxf(__fsub_rn(xx2, xx1), 0.0f);
                        float ih  = fmaxf(__fsub_rn(yy2, yy1), 0.0f);
                        float inter = __fmul_rn(iw, ih);
                        float denom = __fadd_rn(
                            __fsub_rn(__fadd_rn(barea[pi], barea[pj]), inter), 1e-7f);
                        if (__fdiv_rn(inter, denom) > 0.7f) {
                            atomicOr(&mask[i][j >> 5], 1u << (j & 31));
                            atomicOr(&rowAny[i >> 5], 1u << (i & 31));
                        }
                    }
                    j += NT;
                    while (j >= n) { j -= n; ++i; }   // carry (NT/n small)
                }
            }
        }
        __syncthreads();

        // Sparse warp sweep: only rows that suppress something matter (a zero
        // mask row leaves keep unchanged whether or not box i survives).
        // Walk set bits of rowAny in ascending order; lane w<8 owns keep word w.
        if (tid < 32) {
            const int lane = tid;
            unsigned kw = 0;
            if (lane < 8) {
                int lo = lane * 32;
                kw = (n >= lo + 32) ? 0xFFFFFFFFu
                   : (n <= lo ? 0u : ((1u << (n - lo)) - 1u));
            }
#pragma unroll
            for (int w = 0; w < 8; ++w) {
                unsigned ra = rowAny[w];               // broadcast; uniform loop
                while (ra) {
                    int bit = __ffs(ra) - 1;
                    ra &= ra - 1u;
                    int i = w * 32 + bit;
                    unsigned m = (lane < 8) ? mask[i][lane] : 0u;
                    unsigned kwi = __shfl_sync(0xFFFFFFFFu, kw, w);
                    if ((kwi >> bit) & 1u)
                        kw &= ~m;
                }
            }
            if (lane < 8) keepw[lane] = kw;
        }
        __syncthreads();

        // Emit kept rows (slab already zeroed by compact kernel).
        const float SCALE_F = 0.3333333333333333f;
        if (tid < n) {
            int r = tid;
            if ((keepw[r >> 5] >> (r & 31)) & 1u) {
                int pr = perm[r];
                float conf = __uint_as_float((unsigned)(keys[pr] >> 32));
                o[r * 6 + 0] = __fdiv_rn(bx1[pr], SCALE_F);
                o[r * 6 + 1] = __fdiv_rn(by1[pr], SCALE_F);
                o[r * 6 + 2] = __fdiv_rn(bx2[pr], SCALE_F);
                o[r * 6 + 3] = __fdiv_rn(by2[pr], SCALE_F);
                o[r * 6 + 4] = conf;
                // o[r*6+5] stays 0 (cls)
            }
        }
    } else {
        // ---- Fallback (statistically never taken): bitonic sort + sequential NMS ----
        int m = 1; while (m < cnt) m <<= 1;
        for (int i = cnt + tid; i < m; i += NT) keys[i] = 0ull;
        __syncthreads();
        for (int k = 2; k <= m; k <<= 1)
            for (int j = k >> 1; j > 0; j >>= 1) {
                for (int i = tid; i < m; i += NT) {
                    int ixj = i ^ j;
                    if (ixj > i) {
                        unsigned long long u = keys[i], v = keys[ixj];
                        bool desc = ((i & k) == 0);
                        if ((u < v) == desc) { keys[i] = v; keys[ixj] = u; }
                    }
                }
                __syncthreads();
            }
        for (int r = tid; r < n; r += NT) {
            int idx = (int)(0xFFFFFFFFu - (unsigned)keys[r]);
            float cx = p[idx];
            float cy = p[ANCH + idx];
            float w  = p[2 * ANCH + idx];
            float h  = p[3 * ANCH + idx];
            float hw = __fmul_rn(w, 0.5f), hh = __fmul_rn(h, 0.5f);
            float x1 = __fsub_rn(cx, hw), y1 = __fsub_rn(cy, hh);
            float x2 = __fadd_rn(cx, hw), y2 = __fadd_rn(cy, hh);
            bx1[r] = x1; by1[r] = y1; bx2[r] = x2; by2[r] = y2;
            barea[r] = __fmul_rn(__fsub_rn(x2, x1), __fsub_rn(y2, y1));
            keep[r] = 1;
        }
        __syncthreads();
        for (int i = 0; i + 1 < n; ++i) {
            if (keep[i]) {
                float xi1 = bx1[i], yi1 = by1[i], xi2 = bx2[i], yi2 = by2[i];
                float ai  = barea[i];
                for (int j = i + 1 + tid; j < n; j += NT) {
                    if (!keep[j]) continue;
                    float xx1 = fmaxf(xi1, bx1[j]);
                    float yy1 = fmaxf(yi1, by1[j]);
                    float xx2 = fminf(xi2, bx2[j]);
                    float yy2 = fminf(yi2, by2[j]);
                    float iw  = fmaxf(__fsub_rn(xx2, xx1), 0.0f);
                    float ih  = fmaxf(__fsub_rn(yy2, yy1), 0.0f);
                    float inter = __fmul_rn(iw, ih);
                    float denom = __fadd_rn(__fsub_rn(__fadd_rn(ai, barea[j]), inter), 1e-7f);
                    if (__fdiv_rn(inter, denom) > 0.7f) keep[j] = 0;
                }
            }
            __syncthreads();
        }
        const float SCALE_F = 0.3333333333333333f;
        for (int r = tid; r < n; r += NT) {
            if (keep[r]) {
                float conf = __uint_as_float((unsigned)(keys[r] >> 32));
                o[r * 6 + 0] = __fdiv_rn(bx1[r], SCALE_F);
                o[r * 6 + 1] = __fdiv_rn(by1[r], SCALE_F);
                o[r * 6 + 2] = __fdiv_rn(bx2[r], SCALE_F);
                o[r * 6 + 3] = __fdiv_rn(by2[r], SCALE_F);
                o[r * 6 + 4] = conf;
            }
        }
    }
}

extern "C" void kernel_launch(void* const* d_in, const int* in_sizes, int n_in,
                              void* d_out, int out_size) {
    const float* preds = (const float*)d_in[0];
    float* out = (float*)d_out;

    score_compact_kernel<<<(BATCH * ANCH + 255) / 256, 256>>>(preds, out);
    sort_nms_out_kernel<<<BATCH, 1024>>>(preds, out);
}